// round 2
// baseline (speedup 1.0000x reference)
#include <cuda_runtime.h>

#define NN 50000
#define DD 128
#define EE 800000
#define BN_EPS 1e-5f

// Scratch (no allocations allowed): two N x D buffers + BN stats
__device__ float g_buf1[NN * DD];   // agg -> h (pre-BN)
__device__ float g_buf2[NN * DD];   // t = relu(h@W1+b1)
__device__ float g_stats[2 * DD];   // [0:128) col sums, [128:256) col sumsq
__device__ float g_scale[DD];
__device__ float g_shift[DD];
__device__ int g_is64;              // 1 if edge_index is int64, 0 if int32

// k_det: probe edge_index dtype. Indices < 50000 < 2^31, so int64 data has
// zero high words at every odd 32-bit position. Random int32 indices almost
// never hit 0. Deterministic, capture-safe.
__global__ void detect_kernel(const int* __restrict__ ei32) {
    int zeros = 0;
    for (int i = 1; i < 256; i += 2) zeros += (ei32[i] == 0);
    g_is64 = (zeros >= 96) ? 1 : 0;
}

// k0: agg = x (GIN eps=0 -> h = x + sum(msg)), zero stats
__global__ void init_kernel(const float* __restrict__ x) {
    int i = blockIdx.x * blockDim.x + threadIdx.x;
    if (i < NN * DD / 4) {
        ((float4*)g_buf1)[i] = ((const float4*)x)[i];
    }
    if (blockIdx.x == 0 && threadIdx.x < 2 * DD) g_stats[threadIdx.x] = 0.f;
}

// k1: one warp per edge; msg = relu(x[src] + edge_attr); vector-atomic scatter
__global__ void edge_kernel(const float* __restrict__ x,
                            const void* __restrict__ ei,
                            const float* __restrict__ ea) {
    unsigned gt = blockIdx.x * blockDim.x + threadIdx.x;
    unsigned e = gt >> 5;
    int lane = gt & 31;
    if (e >= EE) return;
    long long src, dst;
    if (g_is64) {
        const long long* p = (const long long*)ei;
        src = p[e];
        dst = p[EE + e];
    } else {
        const int* p = (const int*)ei;
        src = p[e];
        dst = p[EE + e];
    }
    if ((unsigned long long)src >= NN || (unsigned long long)dst >= NN) return;
    int c = lane * 4;
    float4 a = *(const float4*)(ea + (size_t)e * DD + c);
    float4 b = *(const float4*)(x + (size_t)src * DD + c);
    float4 v;
    v.x = fmaxf(a.x + b.x, 0.f);
    v.y = fmaxf(a.y + b.y, 0.f);
    v.z = fmaxf(a.z + b.z, 0.f);
    v.w = fmaxf(a.w + b.w, 0.f);
    // sm_90+ 128-bit vector atomic add (global memory)
    atomicAdd((float4*)(g_buf1 + (size_t)dst * DD + c), v);
}

// k2/k3: 128x128 tile GEMM, 256 threads, 8x8 register tile per thread.
// MODE 0: g_buf2 = relu(g_buf1 @ W + b)
// MODE 1: g_buf1 = resid + g_buf2 @ W + b, and accumulate BN column stats
template <int MODE>
__global__ void gemm_kernel(const float* __restrict__ W,
                            const float* __restrict__ bias,
                            const float* __restrict__ resid) {
    extern __shared__ float sm[];
    float(*As)[132] = (float(*)[132])sm;           // [128][132] padded
    float* Ws = sm + 128 * 132;                    // [128][128]

    const float* A = (MODE == 0) ? g_buf1 : g_buf2;
    float* out = (MODE == 0) ? g_buf2 : g_buf1;

    int tid = threadIdx.x;
    int wrp = tid >> 5, ln = tid & 31;
    int row0 = blockIdx.x * 128;

    // cooperative load: A tile (guarded) and full W
#pragma unroll
    for (int rr = 0; rr < 16; rr++) {
        int r = wrp * 16 + rr;
        int gr = row0 + r;
        float4 av = make_float4(0.f, 0.f, 0.f, 0.f);
        if (gr < NN) av = *(const float4*)(A + (size_t)gr * DD + ln * 4);
        *(float4*)&As[r][ln * 4] = av;
        *(float4*)&Ws[r * DD + ln * 4] = *(const float4*)(W + (size_t)r * DD + ln * 4);
    }
    __syncthreads();

    int ty = tid >> 4, tx = tid & 15;
    int m0 = ty * 8, n0 = tx * 8;
    float acc[8][8];
#pragma unroll
    for (int i = 0; i < 8; i++)
#pragma unroll
        for (int j = 0; j < 8; j++) acc[i][j] = 0.f;

#pragma unroll 4
    for (int k = 0; k < 128; k++) {
        float a[8];
#pragma unroll
        for (int i = 0; i < 8; i++) a[i] = As[m0 + i][k];
        float4 w0 = *(float4*)&Ws[k * DD + n0];
        float4 w1 = *(float4*)&Ws[k * DD + n0 + 4];
        float w[8] = {w0.x, w0.y, w0.z, w0.w, w1.x, w1.y, w1.z, w1.w};
#pragma unroll
        for (int i = 0; i < 8; i++)
#pragma unroll
            for (int j = 0; j < 8; j++) acc[i][j] += a[i] * w[j];
    }

    float bl[8];
#pragma unroll
    for (int j = 0; j < 8; j++) bl[j] = bias[n0 + j];

    if (MODE == 0) {
#pragma unroll
        for (int i = 0; i < 8; i++) {
            int gr = row0 + m0 + i;
            if (gr < NN) {
                float4 o0, o1;
                o0.x = fmaxf(acc[i][0] + bl[0], 0.f);
                o0.y = fmaxf(acc[i][1] + bl[1], 0.f);
                o0.z = fmaxf(acc[i][2] + bl[2], 0.f);
                o0.w = fmaxf(acc[i][3] + bl[3], 0.f);
                o1.x = fmaxf(acc[i][4] + bl[4], 0.f);
                o1.y = fmaxf(acc[i][5] + bl[5], 0.f);
                o1.z = fmaxf(acc[i][6] + bl[6], 0.f);
                o1.w = fmaxf(acc[i][7] + bl[7], 0.f);
                *(float4*)(out + (size_t)gr * DD + n0) = o0;
                *(float4*)(out + (size_t)gr * DD + n0 + 4) = o1;
            }
        }
    } else {
        float csum[8], csq[8];
#pragma unroll
        for (int j = 0; j < 8; j++) { csum[j] = 0.f; csq[j] = 0.f; }
#pragma unroll
        for (int i = 0; i < 8; i++) {
            int gr = row0 + m0 + i;
            if (gr < NN) {
                float4 r0 = *(const float4*)(resid + (size_t)gr * DD + n0);
                float4 r1 = *(const float4*)(resid + (size_t)gr * DD + n0 + 4);
                float h[8];
                h[0] = acc[i][0] + bl[0] + r0.x;
                h[1] = acc[i][1] + bl[1] + r0.y;
                h[2] = acc[i][2] + bl[2] + r0.z;
                h[3] = acc[i][3] + bl[3] + r0.w;
                h[4] = acc[i][4] + bl[4] + r1.x;
                h[5] = acc[i][5] + bl[5] + r1.y;
                h[6] = acc[i][6] + bl[6] + r1.z;
                h[7] = acc[i][7] + bl[7] + r1.w;
                float4 o0 = make_float4(h[0], h[1], h[2], h[3]);
                float4 o1 = make_float4(h[4], h[5], h[6], h[7]);
                *(float4*)(out + (size_t)gr * DD + n0) = o0;
                *(float4*)(out + (size_t)gr * DD + n0 + 4) = o1;
#pragma unroll
                for (int j = 0; j < 8; j++) {
                    csum[j] += h[j];
                    csq[j] += h[j] * h[j];
                }
            }
        }
        __syncthreads();  // done reading As/Ws; reuse smem for stats
        float* s = sm;    // [256]
        if (tid < 256) s[tid] = 0.f;
        __syncthreads();
#pragma unroll
        for (int j = 0; j < 8; j++) {
            atomicAdd(&s[n0 + j], csum[j]);
            atomicAdd(&s[DD + n0 + j], csq[j]);
        }
        __syncthreads();
        if (tid < 256) atomicAdd(&g_stats[tid], s[tid]);
    }
}

// k4: per-column BN scale/shift
__global__ void finalize_kernel(const float* __restrict__ gamma,
                                const float* __restrict__ beta) {
    int c = threadIdx.x;
    float mean = g_stats[c] * (1.0f / NN);
    float var = g_stats[DD + c] * (1.0f / NN) - mean * mean;
    float sc = rsqrtf(var + BN_EPS) * gamma[c];
    g_scale[c] = sc;
    g_shift[c] = beta[c] - mean * sc;
}

// k5: out = h * scale + shift
__global__ void norm_kernel(float* __restrict__ out) {
    int i = blockIdx.x * blockDim.x + threadIdx.x;
    if (i >= NN * DD / 4) return;
    float4 v = ((const float4*)g_buf1)[i];
    float4 sc = ((const float4*)g_scale)[i & 31];
    float4 sh = ((const float4*)g_shift)[i & 31];
    v.x = v.x * sc.x + sh.x;
    v.y = v.y * sc.y + sh.y;
    v.z = v.z * sc.z + sh.z;
    v.w = v.w * sc.w + sh.w;
    ((float4*)out)[i] = v;
}

extern "C" void kernel_launch(void* const* d_in, const int* in_sizes, int n_in,
                              void* d_out, int out_size) {
    const float* x = (const float*)d_in[0];
    const void* ei = d_in[1];
    const float* ea = (const float*)d_in[2];
    const float* W1 = (const float*)d_in[3];
    const float* b1 = (const float*)d_in[4];
    const float* W2 = (const float*)d_in[5];
    const float* b2 = (const float*)d_in[6];
    const float* gamma = (const float*)d_in[7];
    const float* beta = (const float*)d_in[8];
    float* out = (float*)d_out;

    const int smem = (128 * 132 + 128 * 128) * 4;  // 133120 B
    cudaFuncSetAttribute(gemm_kernel<0>, cudaFuncAttributeMaxDynamicSharedMemorySize, smem);
    cudaFuncSetAttribute(gemm_kernel<1>, cudaFuncAttributeMaxDynamicSharedMemorySize, smem);

    detect_kernel<<<1, 1>>>((const int*)ei);
    init_kernel<<<(NN * DD / 4 + 255) / 256, 256>>>(x);
    edge_kernel<<<(EE * 32) / 256, 256>>>(x, ei, ea);
    gemm_kernel<0><<<(NN + 127) / 128, 256, smem>>>(W1, b1, nullptr);
    gemm_kernel<1><<<(NN + 127) / 128, 256, smem>>>(W2, b2, x);
    finalize_kernel<<<1, DD>>>(gamma, beta);
    norm_kernel<<<(NN * DD / 4 + 255) / 256, 256>>>(out);
}